// round 2
// baseline (speedup 1.0000x reference)
#include <cuda_runtime.h>
#include <cstdint>

// Problem constants
#define BB 2
#define TT 2048
#define DM 1024
#define NH 16
#define HD 64
#define MROWS (BB * TT)          // 4096

// ---------------- scratch (no allocation allowed) ----------------
__device__ float g_q[MROWS * DM];
__device__ float g_k[MROWS * DM];
__device__ float g_v[MROWS * DM];
__device__ float g_a[MROWS * DM];

// ---------------- SGEMM: C[M,N] = A[M,K] * B[N,K]^T ----------------
// 128x128 tile, K-tile 8, 256 threads, 8x8 per thread.
#define GBM 128
#define GBN 128
#define GBK 8

__global__ __launch_bounds__(256) void sgemm_nt(const float* __restrict__ A,
                                                const float* __restrict__ B,
                                                float* __restrict__ C,
                                                int M, int N, int K) {
    __shared__ float As[GBK][GBM];
    __shared__ float Bs[GBK][GBN];
    const int tid = threadIdx.x;
    const int tx = tid & 15;
    const int ty = tid >> 4;
    const int rowBase = blockIdx.y * GBM;
    const int colBase = blockIdx.x * GBN;
    const int lr = tid >> 1;          // 0..127
    const int lk = (tid & 1) * 4;     // 0 or 4
    const float* Ap = A + (size_t)(rowBase + lr) * K + lk;
    const float* Bp = B + (size_t)(colBase + lr) * K + lk;

    float acc[8][8];
#pragma unroll
    for (int i = 0; i < 8; i++)
#pragma unroll
        for (int j = 0; j < 8; j++) acc[i][j] = 0.0f;

    for (int k0 = 0; k0 < K; k0 += GBK) {
        float4 av = *reinterpret_cast<const float4*>(Ap + k0);
        float4 bv = *reinterpret_cast<const float4*>(Bp + k0);
        As[lk + 0][lr] = av.x; As[lk + 1][lr] = av.y;
        As[lk + 2][lr] = av.z; As[lk + 3][lr] = av.w;
        Bs[lk + 0][lr] = bv.x; Bs[lk + 1][lr] = bv.y;
        Bs[lk + 2][lr] = bv.z; Bs[lk + 3][lr] = bv.w;
        __syncthreads();
#pragma unroll
        for (int kk = 0; kk < GBK; kk++) {
            float ra[8], rb[8];
            *reinterpret_cast<float4*>(&ra[0]) = *reinterpret_cast<const float4*>(&As[kk][ty * 8]);
            *reinterpret_cast<float4*>(&ra[4]) = *reinterpret_cast<const float4*>(&As[kk][ty * 8 + 4]);
            *reinterpret_cast<float4*>(&rb[0]) = *reinterpret_cast<const float4*>(&Bs[kk][tx * 8]);
            *reinterpret_cast<float4*>(&rb[4]) = *reinterpret_cast<const float4*>(&Bs[kk][tx * 8 + 4]);
#pragma unroll
            for (int i = 0; i < 8; i++)
#pragma unroll
                for (int j = 0; j < 8; j++)
                    acc[i][j] += ra[i] * rb[j];
        }
        __syncthreads();
    }

#pragma unroll
    for (int i = 0; i < 8; i++) {
        float* Crow = C + (size_t)(rowBase + ty * 8 + i) * N + colBase + tx * 8;
        *reinterpret_cast<float4*>(&Crow[0]) = make_float4(acc[i][0], acc[i][1], acc[i][2], acc[i][3]);
        *reinterpret_cast<float4*>(&Crow[4]) = make_float4(acc[i][4], acc[i][5], acc[i][6], acc[i][7]);
    }
}

// ---------------- Flash attention (causal, fp32) ----------------
// Grid: (T/64 query tiles, B*H). Block: 256 threads (16x16).
// Br = Bc = 64, head_dim = 64. q/k/v in [B, T, H*HD] layout.
// Dynamic smem: Qs/Ks/Vs/Ps each [64][65] floats.
#define FP 65
#define FTILE 64
#define FSMEM (4 * FTILE * FP * (int)sizeof(float))

__global__ __launch_bounds__(256) void flash_kernel(const float* __restrict__ q,
                                                    const float* __restrict__ k,
                                                    const float* __restrict__ v,
                                                    float* __restrict__ o) {
    extern __shared__ float sm[];
    float* Qs = sm;
    float* Ks = sm + FTILE * FP;
    float* Vs = sm + 2 * FTILE * FP;
    float* Ps = sm + 3 * FTILE * FP;

    const int tid = threadIdx.x;
    const int tx = tid & 15;         // 0..15 -> S cols / O dims (x4)
    const int ty = tid >> 4;         // 0..15 -> S rows (x4)
    const int qt = blockIdx.x;       // query tile
    const int bh = blockIdx.y;
    const int b = bh >> 4;
    const int h = bh & 15;
    const int base = b * TT * DM + h * HD;   // + t*DM + d

    // Load Q tile (pre-scaled by 1/sqrt(HD) = 0.125)
    for (int idx = tid; idx < FTILE * HD; idx += 256) {
        int i = idx >> 6, d = idx & 63;
        Qs[i * FP + d] = q[base + (qt * FTILE + i) * DM + d] * 0.125f;
    }

    float mrow[4], lrow[4], Oa[4][4];
#pragma unroll
    for (int ii = 0; ii < 4; ii++) {
        mrow[ii] = -1e30f;
        lrow[ii] = 0.0f;
#pragma unroll
        for (int jj = 0; jj < 4; jj++) Oa[ii][jj] = 0.0f;
    }

    for (int kt = 0; kt <= qt; kt++) {
        __syncthreads();   // previous PV done (and Q load visible after next sync)
        for (int idx = tid; idx < FTILE * HD; idx += 256) {
            int j = idx >> 6, d = idx & 63;
            int t = kt * FTILE + j;
            Ks[j * FP + d] = k[base + t * DM + d];
            Vs[j * FP + d] = v[base + t * DM + d];
        }
        __syncthreads();

        // S = Q * K^T  (4x4 per thread)
        float s[4][4];
#pragma unroll
        for (int ii = 0; ii < 4; ii++)
#pragma unroll
            for (int jj = 0; jj < 4; jj++) s[ii][jj] = 0.0f;

        for (int d = 0; d < HD; d++) {
            float qa[4], ka[4];
#pragma unroll
            for (int ii = 0; ii < 4; ii++) qa[ii] = Qs[(ty * 4 + ii) * FP + d];
#pragma unroll
            for (int jj = 0; jj < 4; jj++) ka[jj] = Ks[(tx * 4 + jj) * FP + d];
#pragma unroll
            for (int ii = 0; ii < 4; ii++)
#pragma unroll
                for (int jj = 0; jj < 4; jj++)
                    s[ii][jj] += qa[ii] * ka[jj];
        }

        // causal mask on the diagonal tile
        if (kt == qt) {
#pragma unroll
            for (int ii = 0; ii < 4; ii++)
#pragma unroll
                for (int jj = 0; jj < 4; jj++)
                    if (tx * 4 + jj > ty * 4 + ii) s[ii][jj] = -1e30f;
        }

        // online softmax per row (rows owned along ty; reduce across tx via shfl)
#pragma unroll
        for (int ii = 0; ii < 4; ii++) {
            float mx = fmaxf(fmaxf(s[ii][0], s[ii][1]), fmaxf(s[ii][2], s[ii][3]));
            mx = fmaxf(mx, __shfl_xor_sync(0xffffffffu, mx, 1));
            mx = fmaxf(mx, __shfl_xor_sync(0xffffffffu, mx, 2));
            mx = fmaxf(mx, __shfl_xor_sync(0xffffffffu, mx, 4));
            mx = fmaxf(mx, __shfl_xor_sync(0xffffffffu, mx, 8));
            float mn = fmaxf(mrow[ii], mx);
            float corr = __expf(mrow[ii] - mn);
            mrow[ii] = mn;
            float rs = 0.0f;
#pragma unroll
            for (int jj = 0; jj < 4; jj++) {
                float p = __expf(s[ii][jj] - mn);
                rs += p;
                Ps[(ty * 4 + ii) * FP + tx * 4 + jj] = p;
            }
            rs += __shfl_xor_sync(0xffffffffu, rs, 1);
            rs += __shfl_xor_sync(0xffffffffu, rs, 2);
            rs += __shfl_xor_sync(0xffffffffu, rs, 4);
            rs += __shfl_xor_sync(0xffffffffu, rs, 8);
            lrow[ii] = lrow[ii] * corr + rs;
#pragma unroll
            for (int jj = 0; jj < 4; jj++) Oa[ii][jj] *= corr;
        }
        __syncthreads();

        // O += P * V  (dims owned along tx)
        for (int j = 0; j < FTILE; j++) {
            float pa[4], va[4];
#pragma unroll
            for (int ii = 0; ii < 4; ii++) pa[ii] = Ps[(ty * 4 + ii) * FP + j];
#pragma unroll
            for (int jj = 0; jj < 4; jj++) va[jj] = Vs[j * FP + tx * 4 + jj];
#pragma unroll
            for (int ii = 0; ii < 4; ii++)
#pragma unroll
                for (int jj = 0; jj < 4; jj++)
                    Oa[ii][jj] += pa[ii] * va[jj];
        }
    }

    // normalize + write out in [B, T, H*HD] layout
#pragma unroll
    for (int ii = 0; ii < 4; ii++) {
        float inv = 1.0f / lrow[ii];
#pragma unroll
        for (int jj = 0; jj < 4; jj++)
            o[base + (qt * FTILE + ty * 4 + ii) * DM + tx * 4 + jj] = Oa[ii][jj] * inv;
    }
}

// ---------------- launch ----------------
extern "C" void kernel_launch(void* const* d_in, const int* in_sizes, int n_in,
                              void* d_out, int out_size) {
    const float* x  = (const float*)d_in[0];
    const float* Wq = (const float*)d_in[1];
    const float* Wk = (const float*)d_in[2];
    const float* Wv = (const float*)d_in[3];
    const float* Wo = (const float*)d_in[4];
    float* out = (float*)d_out;

    float *qb, *kb, *vb, *ab;
    cudaGetSymbolAddress((void**)&qb, g_q);
    cudaGetSymbolAddress((void**)&kb, g_k);
    cudaGetSymbolAddress((void**)&vb, g_v);
    cudaGetSymbolAddress((void**)&ab, g_a);

    cudaFuncSetAttribute(flash_kernel, cudaFuncAttributeMaxDynamicSharedMemorySize, FSMEM);

    dim3 gGrid(DM / GBN, MROWS / GBM);   // (8, 32)

    sgemm_nt<<<gGrid, 256>>>(x, Wq, qb, MROWS, DM, DM);
    sgemm_nt<<<gGrid, 256>>>(x, Wk, kb, MROWS, DM, DM);
    sgemm_nt<<<gGrid, 256>>>(x, Wv, vb, MROWS, DM, DM);

    dim3 fGrid(TT / FTILE, BB * NH);     // (32, 32)
    flash_kernel<<<fGrid, 256, FSMEM>>>(qb, kb, vb, ab);

    sgemm_nt<<<gGrid, 256>>>(ab, Wo, out, MROWS, DM, DM);
}

// round 6
// speedup vs baseline: 1.5647x; 1.5647x over previous
#include <cuda_runtime.h>
#include <cuda_bf16.h>
#include <cstdint>

// Problem constants
#define BB 2
#define TT 2048
#define DM 1024
#define NH 16
#define HD 64
#define MROWS (BB * TT)          // 4096
#define NELEM_X (MROWS * DM)     // 4194304
#define NELEM_W (DM * DM)        // 1048576

// ---------------- scratch (no allocation allowed) ----------------
__device__ float g_q[NELEM_X];
__device__ float g_k[NELEM_X];
__device__ float g_v[NELEM_X];
__device__ float g_a[NELEM_X];
__device__ __nv_bfloat16 g_xhi[NELEM_X], g_xlo[NELEM_X];
__device__ __nv_bfloat16 g_ahi[NELEM_X], g_alo[NELEM_X];
__device__ __nv_bfloat16 g_whi[4][NELEM_W], g_wlo[4][NELEM_W];

// ---------------- helpers ----------------
__device__ __forceinline__ uint32_t smem_u32(const void* p) {
    uint32_t a;
    asm("{ .reg .u64 t; cvta.to.shared.u64 t, %1; cvt.u32.u64 %0, t; }" : "=r"(a) : "l"(p));
    return a;
}
__device__ __forceinline__ void cp_async16(uint32_t saddr, const void* gptr) {
    asm volatile("cp.async.cg.shared.global [%0], [%1], 16;" :: "r"(saddr), "l"(gptr));
}
__device__ __forceinline__ void ldsm4(uint32_t* r, uint32_t addr) {
    asm volatile("ldmatrix.sync.aligned.m8n8.x4.shared.b16 {%0,%1,%2,%3}, [%4];"
                 : "=r"(r[0]), "=r"(r[1]), "=r"(r[2]), "=r"(r[3]) : "r"(addr));
}
__device__ __forceinline__ void ldsm2(uint32_t* r, uint32_t addr) {
    asm volatile("ldmatrix.sync.aligned.m8n8.x2.shared.b16 {%0,%1}, [%2];"
                 : "=r"(r[0]), "=r"(r[1]) : "r"(addr));
}
__device__ __forceinline__ void mma16816(float* d, const uint32_t* a, const uint32_t* b) {
    asm volatile("mma.sync.aligned.m16n8k16.row.col.f32.bf16.bf16.f32 "
                 "{%0,%1,%2,%3},{%4,%5,%6,%7},{%8,%9},{%0,%1,%2,%3};"
                 : "+f"(d[0]), "+f"(d[1]), "+f"(d[2]), "+f"(d[3])
                 : "r"(a[0]), "r"(a[1]), "r"(a[2]), "r"(a[3]), "r"(b[0]), "r"(b[1]));
}

// ---------------- split fp32 -> bf16 hi/lo ----------------
__global__ __launch_bounds__(256) void split_kernel(const float* __restrict__ in,
                                                    __nv_bfloat16* __restrict__ hi,
                                                    __nv_bfloat16* __restrict__ lo,
                                                    int n4) {
    int i = blockIdx.x * 256 + threadIdx.x;
    if (i >= n4) return;
    float4 v = reinterpret_cast<const float4*>(in)[i];
    __nv_bfloat16 h0 = __float2bfloat16(v.x);
    __nv_bfloat16 h1 = __float2bfloat16(v.y);
    __nv_bfloat16 h2 = __float2bfloat16(v.z);
    __nv_bfloat16 h3 = __float2bfloat16(v.w);
    __nv_bfloat16 l0 = __float2bfloat16(v.x - __bfloat162float(h0));
    __nv_bfloat16 l1 = __float2bfloat16(v.y - __bfloat162float(h1));
    __nv_bfloat16 l2 = __float2bfloat16(v.z - __bfloat162float(h2));
    __nv_bfloat16 l3 = __float2bfloat16(v.w - __bfloat162float(h3));
    __nv_bfloat162* hp = reinterpret_cast<__nv_bfloat162*>(hi);
    __nv_bfloat162* lp = reinterpret_cast<__nv_bfloat162*>(lo);
    hp[2 * i + 0] = __nv_bfloat162(h0, h1);
    hp[2 * i + 1] = __nv_bfloat162(h2, h3);
    lp[2 * i + 0] = __nv_bfloat162(l0, l1);
    lp[2 * i + 1] = __nv_bfloat162(l2, l3);
}

// ---------------- mma.sync bf16x3 GEMM: C[M,N] = (Ahi+Alo)[M,K] * (Bhi+Blo)[N,K]^T ----
// 128x128 CTA tile, 8 warps (each 64x32 = 4x4 m16n8k16 tiles), K-chunk 32,
// 2-stage cp.async pipeline. Smem rows padded to 80 B (conflict-free ldmatrix).
#define GKC 32                       // K elements per chunk
#define ROWB 80                      // bytes per smem row (32 bf16 data + pad)
#define BUFB (128 * ROWB)            // 10240 per buffer
#define STGB (4 * BUFB)              // Ah, Al, Bh, Bl per stage
#define GSMEM (2 * STGB)             // 81920

__global__ __launch_bounds__(256) void gemm_mma(const __nv_bfloat16* __restrict__ Ahi,
                                                const __nv_bfloat16* __restrict__ Alo,
                                                const __nv_bfloat16* __restrict__ Bhi,
                                                const __nv_bfloat16* __restrict__ Blo,
                                                float* __restrict__ C,
                                                int M, int N, int K) {
    extern __shared__ char smem[];
    const uint32_t sbase = smem_u32(smem);
    const int tid = threadIdx.x;
    const int wid = tid >> 5;
    const int lane = tid & 31;
    const int warp_m = (wid & 1) * 64;
    const int warp_n = (wid >> 1) * 32;
    const int rowBase = blockIdx.y * 128;
    const int colBase = blockIdx.x * 128;

    const __nv_bfloat16* srcs[4];
    srcs[0] = Ahi + (size_t)rowBase * K;
    srcs[1] = Alo + (size_t)rowBase * K;
    srcs[2] = Bhi + (size_t)colBase * K;
    srcs[3] = Blo + (size_t)colBase * K;

    float acc[16][4];
#pragma unroll
    for (int i = 0; i < 16; i++)
#pragma unroll
        for (int j = 0; j < 4; j++) acc[i][j] = 0.0f;

    const int NCH = K / GKC;   // 32

    // issue loads for one chunk into stage (chunk & 1)
    auto issue = [&](int chunk) {
        const uint32_t stb = sbase + (uint32_t)(chunk & 1) * STGB;
        const int k0 = chunk * GKC;
#pragma unroll
        for (int t = 0; t < 8; t++) {
            int idx = tid + t * 256;        // 0..2047 16B chunks (4 buf x 512)
            int b = idx >> 9;
            int pos = idx & 511;
            int r = pos >> 2;
            int c8 = pos & 3;
            cp_async16(stb + (uint32_t)b * BUFB + (uint32_t)(r * ROWB + c8 * 16),
                       srcs[b] + (size_t)r * K + k0 + c8 * 8);
        }
        asm volatile("cp.async.commit_group;" ::: "memory");
    };

    issue(0);
    for (int i = 0; i < NCH; i++) {
        if (i + 1 < NCH) {
            issue(i + 1);
            asm volatile("cp.async.wait_group 1;" ::: "memory");
        } else {
            asm volatile("cp.async.wait_group 0;" ::: "memory");
        }
        __syncthreads();

        const uint32_t stb = sbase + (uint32_t)(i & 1) * STGB;
        const int lm = lane & 15, lk = lane >> 4;
        const int ln = lane & 7, lkb = (lane >> 3) & 1;
#pragma unroll
        for (int ks = 0; ks < 2; ks++) {
            uint32_t ah[4][4], al[4][4], bh[4][2], bl[4][2];
#pragma unroll
            for (int mt = 0; mt < 4; mt++) {
                uint32_t ra = stb + (uint32_t)((warp_m + mt * 16 + lm) * ROWB + ks * 32 + lk * 16);
                ldsm4(ah[mt], ra);
                ldsm4(al[mt], ra + BUFB);
            }
#pragma unroll
            for (int nt = 0; nt < 4; nt++) {
                uint32_t rb = stb + 2 * BUFB + (uint32_t)((warp_n + nt * 8 + ln) * ROWB + ks * 32 + lkb * 16);
                ldsm2(bh[nt], rb);
                ldsm2(bl[nt], rb + BUFB);
            }
#pragma unroll
            for (int mt = 0; mt < 4; mt++)
#pragma unroll
                for (int nt = 0; nt < 4; nt++) {
                    mma16816(acc[mt * 4 + nt], ah[mt], bh[nt]);
                    mma16816(acc[mt * 4 + nt], ah[mt], bl[nt]);
                    mma16816(acc[mt * 4 + nt], al[mt], bh[nt]);
                }
        }
        __syncthreads();   // compute done before stage is overwritten at i+2
    }

    // epilogue: c0,c1 -> (m, n..n+1); c2,c3 -> (m+8, n..n+1)
    const int mrow = rowBase + warp_m + (lane >> 2);
    const int ncol = colBase + warp_n + (lane & 3) * 2;
#pragma unroll
    for (int mt = 0; mt < 4; mt++)
#pragma unroll
        for (int nt = 0; nt < 4; nt++) {
            float* p = C + (size_t)(mrow + mt * 16) * N + ncol + nt * 8;
            *reinterpret_cast<float2*>(p) = make_float2(acc[mt * 4 + nt][0], acc[mt * 4 + nt][1]);
            *reinterpret_cast<float2*>(p + 8 * (size_t)N) = make_float2(acc[mt * 4 + nt][2], acc[mt * 4 + nt][3]);
        }
}

// ---------------- Flash attention (causal, fp32) — unchanged ----------------
#define FP 65
#define FTILE 64
#define FSMEM (4 * FTILE * FP * (int)sizeof(float))

__global__ __launch_bounds__(256) void flash_kernel(const float* __restrict__ q,
                                                    const float* __restrict__ k,
                                                    const float* __restrict__ v,
                                                    float* __restrict__ o) {
    extern __shared__ float sm[];
    float* Qs = sm;
    float* Ks = sm + FTILE * FP;
    float* Vs = sm + 2 * FTILE * FP;
    float* Ps = sm + 3 * FTILE * FP;

    const int tid = threadIdx.x;
    const int tx = tid & 15;
    const int ty = tid >> 4;
    const int qt = blockIdx.x;
    const int bh = blockIdx.y;
    const int b = bh >> 4;
    const int h = bh & 15;
    const int base = b * TT * DM + h * HD;

    for (int idx = tid; idx < FTILE * HD; idx += 256) {
        int i = idx >> 6, d = idx & 63;
        Qs[i * FP + d] = q[base + (qt * FTILE + i) * DM + d] * 0.125f;
    }

    float mrow[4], lrow[4], Oa[4][4];
#pragma unroll
    for (int ii = 0; ii < 4; ii++) {
        mrow[ii] = -1e30f;
        lrow[ii] = 0.0f;
#pragma unroll
        for (int jj = 0; jj < 4; jj++) Oa[ii][jj] = 0.0f;
    }

    for (int kt = 0; kt <= qt; kt++) {
        __syncthreads();
        for (int idx = tid; idx < FTILE * HD; idx += 256) {
            int j = idx >> 6, d = idx & 63;
            int t = kt * FTILE + j;
            Ks[j * FP + d] = k[base + t * DM + d];
            Vs[j * FP + d] = v[base + t * DM + d];
        }
        __syncthreads();

        float s[4][4];
#pragma unroll
        for (int ii = 0; ii < 4; ii++)
#pragma unroll
            for (int jj = 0; jj < 4; jj++) s[ii][jj] = 0.0f;

        for (int d = 0; d < HD; d++) {
            float qa[4], ka[4];
#pragma unroll
            for (int ii = 0; ii < 4; ii++) qa[ii] = Qs[(ty * 4 + ii) * FP + d];
#pragma unroll
            for (int jj = 0; jj < 4; jj++) ka[jj] = Ks[(tx * 4 + jj) * FP + d];
#pragma unroll
            for (int ii = 0; ii < 4; ii++)
#pragma unroll
                for (int jj = 0; jj < 4; jj++)
                    s[ii][jj] += qa[ii] * ka[jj];
        }

        if (kt == qt) {
#pragma unroll
            for (int ii = 0; ii < 4; ii++)
#pragma unroll
                for (int jj = 0; jj < 4; jj++)
                    if (tx * 4 + jj > ty * 4 + ii) s[ii][jj] = -1e30f;
        }

#pragma unroll
        for (int ii = 0; ii < 4; ii++) {
            float mx = fmaxf(fmaxf(s[ii][0], s[ii][1]), fmaxf(s[ii][2], s[ii][3]));
            mx = fmaxf(mx, __shfl_xor_sync(0xffffffffu, mx, 1));
            mx = fmaxf(mx, __shfl_xor_sync(0xffffffffu, mx, 2));
            mx = fmaxf(mx, __shfl_xor_sync(0xffffffffu, mx, 4));
            mx = fmaxf(mx, __shfl_xor_sync(0xffffffffu, mx, 8));
            float mn = fmaxf(mrow[ii], mx);
            float corr = __expf(mrow[ii] - mn);
            mrow[ii] = mn;
            float rs = 0.0f;
#pragma unroll
            for (int jj = 0; jj < 4; jj++) {
                float p = __expf(s[ii][jj] - mn);
                rs += p;
                Ps[(ty * 4 + ii) * FP + tx * 4 + jj] = p;
            }
            rs += __shfl_xor_sync(0xffffffffu, rs, 1);
            rs += __shfl_xor_sync(0xffffffffu, rs, 2);
            rs += __shfl_xor_sync(0xffffffffu, rs, 4);
            rs += __shfl_xor_sync(0xffffffffu, rs, 8);
            lrow[ii] = lrow[ii] * corr + rs;
#pragma unroll
            for (int jj = 0; jj < 4; jj++) Oa[ii][jj] *= corr;
        }
        __syncthreads();

        for (int j = 0; j < FTILE; j++) {
            float pa[4], va[4];
#pragma unroll
            for (int ii = 0; ii < 4; ii++) pa[ii] = Ps[(ty * 4 + ii) * FP + j];
#pragma unroll
            for (int jj = 0; jj < 4; jj++) va[jj] = Vs[j * FP + tx * 4 + jj];
#pragma unroll
            for (int ii = 0; ii < 4; ii++)
#pragma unroll
                for (int jj = 0; jj < 4; jj++)
                    Oa[ii][jj] += pa[ii] * va[jj];
        }
    }

#pragma unroll
    for (int ii = 0; ii < 4; ii++) {
        float inv = 1.0f / lrow[ii];
#pragma unroll
        for (int jj = 0; jj < 4; jj++)
            o[base + (qt * FTILE + ty * 4 + ii) * DM + tx * 4 + jj] = Oa[ii][jj] * inv;
    }
}

// ---------------- launch ----------------
extern "C" void kernel_launch(void* const* d_in, const int* in_sizes, int n_in,
                              void* d_out, int out_size) {
    const float* x  = (const float*)d_in[0];
    const float* W[4] = {(const float*)d_in[1], (const float*)d_in[2],
                         (const float*)d_in[3], (const float*)d_in[4]};
    float* out = (float*)d_out;

    float *qb, *kb, *vb, *ab;
    cudaGetSymbolAddress((void**)&qb, g_q);
    cudaGetSymbolAddress((void**)&kb, g_k);
    cudaGetSymbolAddress((void**)&vb, g_v);
    cudaGetSymbolAddress((void**)&ab, g_a);
    __nv_bfloat16 *xhi, *xlo, *ahi, *alo, *whi, *wlo;
    cudaGetSymbolAddress((void**)&xhi, g_xhi);
    cudaGetSymbolAddress((void**)&xlo, g_xlo);
    cudaGetSymbolAddress((void**)&ahi, g_ahi);
    cudaGetSymbolAddress((void**)&alo, g_alo);
    cudaGetSymbolAddress((void**)&whi, g_whi);
    cudaGetSymbolAddress((void**)&wlo, g_wlo);

    cudaFuncSetAttribute(flash_kernel, cudaFuncAttributeMaxDynamicSharedMemorySize, FSMEM);
    cudaFuncSetAttribute(gemm_mma, cudaFuncAttributeMaxDynamicSharedMemorySize, GSMEM);

    // splits
    split_kernel<<<NELEM_X / 4 / 256, 256>>>(x, xhi, xlo, NELEM_X / 4);
    for (int i = 0; i < 4; i++)
        split_kernel<<<NELEM_W / 4 / 256, 256>>>(W[i], whi + (size_t)i * NELEM_W,
                                                 wlo + (size_t)i * NELEM_W, NELEM_W / 4);

    dim3 gGrid(DM / 128, MROWS / 128);   // (8, 32)
    float* qkv[3] = {qb, kb, vb};
    for (int i = 0; i < 3; i++)
        gemm_mma<<<gGrid, 256, GSMEM>>>(xhi, xlo,
                                        whi + (size_t)i * NELEM_W, wlo + (size_t)i * NELEM_W,
                                        qkv[i], MROWS, DM, DM);

    dim3 fGrid(TT / FTILE, BB * NH);     // (32, 32)
    flash_kernel<<<fGrid, 256, FSMEM>>>(qb, kb, vb, ab);

    split_kernel<<<NELEM_X / 4 / 256, 256>>>(ab, ahi, alo, NELEM_X / 4);
    gemm_mma<<<gGrid, 256, GSMEM>>>(ahi, alo,
                                    whi + (size_t)3 * NELEM_W, wlo + (size_t)3 * NELEM_W,
                                    out, MROWS, DM, DM);
}

// round 7
// speedup vs baseline: 2.8685x; 1.8332x over previous
#include <cuda_runtime.h>
#include <cuda_bf16.h>
#include <cstdint>

// Problem constants
#define BB 2
#define TT 2048
#define DM 1024
#define NH 16
#define HD 64
#define MROWS (BB * TT)          // 4096
#define NELEM_X (MROWS * DM)     // 4194304
#define NELEM_W (DM * DM)        // 1048576

// ---------------- scratch (no allocation allowed) ----------------
__device__ __nv_bfloat16 g_qhi[NELEM_X], g_qlo[NELEM_X];
__device__ __nv_bfloat16 g_khi[NELEM_X], g_klo[NELEM_X];
__device__ __nv_bfloat16 g_vhi[NELEM_X], g_vlo[NELEM_X];
__device__ __nv_bfloat16 g_ahi[NELEM_X], g_alo[NELEM_X];
__device__ __nv_bfloat16 g_xhi[NELEM_X], g_xlo[NELEM_X];
__device__ __nv_bfloat16 g_whi[4][NELEM_W], g_wlo[4][NELEM_W];

// ---------------- helpers ----------------
__device__ __forceinline__ uint32_t smem_u32(const void* p) {
    uint32_t a;
    asm("{ .reg .u64 t; cvta.to.shared.u64 t, %1; cvt.u32.u64 %0, t; }" : "=r"(a) : "l"(p));
    return a;
}
__device__ __forceinline__ void cp_async16(uint32_t saddr, const void* gptr) {
    asm volatile("cp.async.cg.shared.global [%0], [%1], 16;" :: "r"(saddr), "l"(gptr));
}
__device__ __forceinline__ void ldsm4(uint32_t* r, uint32_t addr) {
    asm volatile("ldmatrix.sync.aligned.m8n8.x4.shared.b16 {%0,%1,%2,%3}, [%4];"
                 : "=r"(r[0]), "=r"(r[1]), "=r"(r[2]), "=r"(r[3]) : "r"(addr));
}
__device__ __forceinline__ void ldsm2(uint32_t* r, uint32_t addr) {
    asm volatile("ldmatrix.sync.aligned.m8n8.x2.shared.b16 {%0,%1}, [%2];"
                 : "=r"(r[0]), "=r"(r[1]) : "r"(addr));
}
__device__ __forceinline__ void ldsm2t(uint32_t* r, uint32_t addr) {
    asm volatile("ldmatrix.sync.aligned.m8n8.x2.trans.shared.b16 {%0,%1}, [%2];"
                 : "=r"(r[0]), "=r"(r[1]) : "r"(addr));
}
__device__ __forceinline__ void mma16816(float* d, const uint32_t* a, const uint32_t* b) {
    asm volatile("mma.sync.aligned.m16n8k16.row.col.f32.bf16.bf16.f32 "
                 "{%0,%1,%2,%3},{%4,%5,%6,%7},{%8,%9},{%0,%1,%2,%3};"
                 : "+f"(d[0]), "+f"(d[1]), "+f"(d[2]), "+f"(d[3])
                 : "r"(a[0]), "r"(a[1]), "r"(a[2]), "r"(a[3]), "r"(b[0]), "r"(b[1]));
}
// split two fp32 into packed bf16x2 hi + lo (low half = first value)
__device__ __forceinline__ void split_pack(float a, float b, uint32_t& hp, uint32_t& lp) {
    __nv_bfloat16 ha = __float2bfloat16(a), hb = __float2bfloat16(b);
    __nv_bfloat16 la = __float2bfloat16(a - __bfloat162float(ha));
    __nv_bfloat16 lb = __float2bfloat16(b - __bfloat162float(hb));
    hp = ((uint32_t)__bfloat16_as_ushort(hb) << 16) | __bfloat16_as_ushort(ha);
    lp = ((uint32_t)__bfloat16_as_ushort(lb) << 16) | __bfloat16_as_ushort(la);
}

// ---------------- split fp32 -> bf16 hi/lo ----------------
__global__ __launch_bounds__(256) void split_kernel(const float* __restrict__ in,
                                                    __nv_bfloat16* __restrict__ hi,
                                                    __nv_bfloat16* __restrict__ lo,
                                                    int n4) {
    int i = blockIdx.x * 256 + threadIdx.x;
    if (i >= n4) return;
    float4 v = reinterpret_cast<const float4*>(in)[i];
    uint32_t h0, l0, h1, l1;
    split_pack(v.x, v.y, h0, l0);
    split_pack(v.z, v.w, h1, l1);
    uint32_t* hp = reinterpret_cast<uint32_t*>(hi);
    uint32_t* lp = reinterpret_cast<uint32_t*>(lo);
    hp[2 * i + 0] = h0; hp[2 * i + 1] = h1;
    lp[2 * i + 0] = l0; lp[2 * i + 1] = l1;
}

// ---------------- mma.sync bf16x3 GEMM: C = (Ahi+Alo)(Bhi+Blo)^T --------------
// 128x128 CTA tile, 8 warps (64x32 each), K-chunk 32, 2-stage cp.async pipeline.
// SPLITOUT: write bf16 hi/lo outputs instead of fp32.
#define GKC 32
#define ROWB 80
#define BUFB (128 * ROWB)            // 10240
#define STGB (4 * BUFB)
#define GSMEM (2 * STGB)             // 81920

template<bool SPLITOUT>
__global__ __launch_bounds__(256) void gemm_mma(const __nv_bfloat16* __restrict__ Ahi,
                                                const __nv_bfloat16* __restrict__ Alo,
                                                const __nv_bfloat16* __restrict__ Bhi,
                                                const __nv_bfloat16* __restrict__ Blo,
                                                float* __restrict__ C,
                                                __nv_bfloat16* __restrict__ Chi,
                                                __nv_bfloat16* __restrict__ Clo,
                                                int M, int N, int K) {
    extern __shared__ char smem[];
    const uint32_t sbase = smem_u32(smem);
    const int tid = threadIdx.x;
    const int wid = tid >> 5;
    const int lane = tid & 31;
    const int warp_m = (wid & 1) * 64;
    const int warp_n = (wid >> 1) * 32;
    const int rowBase = blockIdx.y * 128;
    const int colBase = blockIdx.x * 128;

    const __nv_bfloat16* srcs[4];
    srcs[0] = Ahi + (size_t)rowBase * K;
    srcs[1] = Alo + (size_t)rowBase * K;
    srcs[2] = Bhi + (size_t)colBase * K;
    srcs[3] = Blo + (size_t)colBase * K;

    float acc[16][4];
#pragma unroll
    for (int i = 0; i < 16; i++)
#pragma unroll
        for (int j = 0; j < 4; j++) acc[i][j] = 0.0f;

    const int NCH = K / GKC;   // 32

    auto issue = [&](int chunk) {
        const uint32_t stb = sbase + (uint32_t)(chunk & 1) * STGB;
        const int k0 = chunk * GKC;
#pragma unroll
        for (int t = 0; t < 8; t++) {
            int idx = tid + t * 256;
            int b = idx >> 9;
            int pos = idx & 511;
            int r = pos >> 2;
            int c8 = pos & 3;
            cp_async16(stb + (uint32_t)b * BUFB + (uint32_t)(r * ROWB + c8 * 16),
                       srcs[b] + (size_t)r * K + k0 + c8 * 8);
        }
        asm volatile("cp.async.commit_group;" ::: "memory");
    };

    issue(0);
    for (int i = 0; i < NCH; i++) {
        if (i + 1 < NCH) {
            issue(i + 1);
            asm volatile("cp.async.wait_group 1;" ::: "memory");
        } else {
            asm volatile("cp.async.wait_group 0;" ::: "memory");
        }
        __syncthreads();

        const uint32_t stb = sbase + (uint32_t)(i & 1) * STGB;
        const int lm = lane & 15, lk = lane >> 4;
        const int ln = lane & 7, lkb = (lane >> 3) & 1;
#pragma unroll
        for (int ks = 0; ks < 2; ks++) {
            uint32_t ah[4][4], al[4][4], bh[4][2], bl[4][2];
#pragma unroll
            for (int mt = 0; mt < 4; mt++) {
                uint32_t ra = stb + (uint32_t)((warp_m + mt * 16 + lm) * ROWB + ks * 32 + lk * 16);
                ldsm4(ah[mt], ra);
                ldsm4(al[mt], ra + BUFB);
            }
#pragma unroll
            for (int nt = 0; nt < 4; nt++) {
                uint32_t rb = stb + 2 * BUFB + (uint32_t)((warp_n + nt * 8 + ln) * ROWB + ks * 32 + lkb * 16);
                ldsm2(bh[nt], rb);
                ldsm2(bl[nt], rb + BUFB);
            }
#pragma unroll
            for (int mt = 0; mt < 4; mt++)
#pragma unroll
                for (int nt = 0; nt < 4; nt++) {
                    mma16816(acc[mt * 4 + nt], ah[mt], bh[nt]);
                    mma16816(acc[mt * 4 + nt], ah[mt], bl[nt]);
                    mma16816(acc[mt * 4 + nt], al[mt], bh[nt]);
                }
        }
        __syncthreads();
    }

    const int mrow = rowBase + warp_m + (lane >> 2);
    const int ncol = colBase + warp_n + (lane & 3) * 2;
#pragma unroll
    for (int mt = 0; mt < 4; mt++)
#pragma unroll
        for (int nt = 0; nt < 4; nt++) {
            const float* a = acc[mt * 4 + nt];
            size_t p0 = (size_t)(mrow + mt * 16) * N + ncol + nt * 8;
            size_t p1 = p0 + 8 * (size_t)N;
            if (!SPLITOUT) {
                *reinterpret_cast<float2*>(C + p0) = make_float2(a[0], a[1]);
                *reinterpret_cast<float2*>(C + p1) = make_float2(a[2], a[3]);
            } else {
                uint32_t hp, lp;
                split_pack(a[0], a[1], hp, lp);
                *reinterpret_cast<uint32_t*>(Chi + p0) = hp;
                *reinterpret_cast<uint32_t*>(Clo + p0) = lp;
                split_pack(a[2], a[3], hp, lp);
                *reinterpret_cast<uint32_t*>(Chi + p1) = hp;
                *reinterpret_cast<uint32_t*>(Clo + p1) = lp;
            }
        }
}

// ---------------- Flash attention via mma.sync (causal) ----------------
// Br=128 queries/CTA, Bc=64 keys/iter, D=64. 8 warps, warp w owns rows 16w..16w+15
// and the full key width (softmax fully warp-local). bf16x3 for QK^T and PV.
#define FBR 128
#define FBC 64
#define FROWB 144                    // 64 bf16 = 128B + 16B pad
#define QBUF (FBR * FROWB)           // 18432
#define KVBUF (FBC * FROWB)          // 9216
#define FKV0 (2 * QBUF)              // 36864
#define FSTG (4 * KVBUF)             // 36864
#define FSMEM2 (FKV0 + 2 * FSTG)     // 110592

__global__ __launch_bounds__(256, 1) void flash_mma(
    const __nv_bfloat16* __restrict__ qh, const __nv_bfloat16* __restrict__ ql,
    const __nv_bfloat16* __restrict__ kh, const __nv_bfloat16* __restrict__ kl,
    const __nv_bfloat16* __restrict__ vh, const __nv_bfloat16* __restrict__ vl,
    __nv_bfloat16* __restrict__ oh, __nv_bfloat16* __restrict__ ol) {
    extern __shared__ char smem[];
    const uint32_t sbase = smem_u32(smem);
    const int tid = threadIdx.x;
    const int wid = tid >> 5;
    const int lane = tid & 31;
    const int qt = blockIdx.x;
    const int bh = blockIdx.y;
    const int b = bh >> 4, h = bh & 15;
    const size_t base = (size_t)b * TT * DM + h * HD;
    const int q0 = qt * FBR;

    // Q hi/lo -> smem (2048 16B chunks)
#pragma unroll
    for (int t = 0; t < 8; t++) {
        int idx = tid + t * 256;
        int mat = idx >> 10;
        int pos = idx & 1023;
        int r = pos >> 3, c8 = pos & 7;
        const __nv_bfloat16* src = (mat ? ql : qh) + base + (size_t)(q0 + r) * DM + c8 * 8;
        cp_async16(sbase + (uint32_t)(mat * QBUF + r * FROWB + c8 * 16), src);
    }
    asm volatile("cp.async.commit_group;" ::: "memory");

    const __nv_bfloat16* mats[4] = {kh, kl, vh, vl};
    auto issue_kv = [&](int kt) {
        const uint32_t stb = sbase + FKV0 + (uint32_t)(kt & 1) * FSTG;
        const int t0 = kt * FBC;
#pragma unroll
        for (int t = 0; t < 8; t++) {
            int idx = tid + t * 256;               // 4 mats x 64 rows x 8 chunks
            int mat = idx >> 9;
            int pos = idx & 511;
            int r = pos >> 3, c8 = pos & 7;
            cp_async16(stb + (uint32_t)(mat * KVBUF + r * FROWB + c8 * 16),
                       mats[mat] + base + (size_t)(t0 + r) * DM + c8 * 8);
        }
        asm volatile("cp.async.commit_group;" ::: "memory");
    };

    issue_kv(0);
    asm volatile("cp.async.wait_group 0;" ::: "memory");
    __syncthreads();

    // Q fragments (persistent in registers)
    uint32_t qfh[4][4], qfl[4][4];
#pragma unroll
    for (int ks = 0; ks < 4; ks++) {
        uint32_t a = sbase + (uint32_t)((wid * 16 + (lane & 15)) * FROWB + ks * 32 + (lane >> 4) * 16);
        ldsm4(qfh[ks], a);
        ldsm4(qfl[ks], a + QBUF);
    }

    float m0 = -1e30f, m1 = -1e30f, l0 = 0.0f, l1 = 0.0f;
    float oacc[8][4];
#pragma unroll
    for (int i = 0; i < 8; i++)
#pragma unroll
        for (int j = 0; j < 4; j++) oacc[i][j] = 0.0f;

    const int NKT = 2 * (qt + 1);
    for (int kt = 0; kt < NKT; kt++) {
        if (kt + 1 < NKT) {
            issue_kv(kt + 1);
            asm volatile("cp.async.wait_group 1;" ::: "memory");
        } else {
            asm volatile("cp.async.wait_group 0;" ::: "memory");
        }
        __syncthreads();
        const uint32_t stb = sbase + FKV0 + (uint32_t)(kt & 1) * FSTG;

        // S = Q K^T (bf16x3)
        float s[8][4];
#pragma unroll
        for (int i = 0; i < 8; i++)
#pragma unroll
            for (int j = 0; j < 4; j++) s[i][j] = 0.0f;
#pragma unroll
        for (int ks = 0; ks < 4; ks++) {
#pragma unroll
            for (int nt = 0; nt < 8; nt++) {
                uint32_t a = stb + (uint32_t)((nt * 8 + (lane & 7)) * FROWB + ks * 32 + ((lane >> 3) & 1) * 16);
                uint32_t kh2[2], kl2[2];
                ldsm2(kh2, a);
                ldsm2(kl2, a + KVBUF);
                mma16816(s[nt], qfh[ks], kh2);
                mma16816(s[nt], qfh[ks], kl2);
                mma16816(s[nt], qfl[ks], kh2);
            }
        }

        // scale + causal mask
        const int r0g = q0 + wid * 16 + (lane >> 2);
        const bool need_mask = (kt >= 2 * qt);
#pragma unroll
        for (int nt = 0; nt < 8; nt++)
#pragma unroll
            for (int c = 0; c < 4; c++) {
                float val = s[nt][c] * 0.125f;
                if (need_mask) {
                    int col = kt * 64 + nt * 8 + (lane & 3) * 2 + (c & 1);
                    int row = r0g + (c >> 1) * 8;
                    if (col > row) val = -1e30f;
                }
                s[nt][c] = val;
            }

        // online softmax (rows r0 -> regs c0,c1; r0+8 -> c2,c3; 4-lane groups share rows)
        float mx0 = -1e30f, mx1 = -1e30f;
#pragma unroll
        for (int nt = 0; nt < 8; nt++) {
            mx0 = fmaxf(mx0, fmaxf(s[nt][0], s[nt][1]));
            mx1 = fmaxf(mx1, fmaxf(s[nt][2], s[nt][3]));
        }
        mx0 = fmaxf(mx0, __shfl_xor_sync(0xffffffffu, mx0, 1));
        mx0 = fmaxf(mx0, __shfl_xor_sync(0xffffffffu, mx0, 2));
        mx1 = fmaxf(mx1, __shfl_xor_sync(0xffffffffu, mx1, 1));
        mx1 = fmaxf(mx1, __shfl_xor_sync(0xffffffffu, mx1, 2));
        float nm0 = fmaxf(m0, mx0), nm1 = fmaxf(m1, mx1);
        float cr0 = __expf(m0 - nm0), cr1 = __expf(m1 - nm1);
        m0 = nm0; m1 = nm1;
        float rs0 = 0.0f, rs1 = 0.0f;
#pragma unroll
        for (int nt = 0; nt < 8; nt++) {
            s[nt][0] = __expf(s[nt][0] - nm0);
            s[nt][1] = __expf(s[nt][1] - nm0);
            s[nt][2] = __expf(s[nt][2] - nm1);
            s[nt][3] = __expf(s[nt][3] - nm1);
            rs0 += s[nt][0] + s[nt][1];
            rs1 += s[nt][2] + s[nt][3];
        }
        rs0 += __shfl_xor_sync(0xffffffffu, rs0, 1);
        rs0 += __shfl_xor_sync(0xffffffffu, rs0, 2);
        rs1 += __shfl_xor_sync(0xffffffffu, rs1, 1);
        rs1 += __shfl_xor_sync(0xffffffffu, rs1, 2);
        l0 = l0 * cr0 + rs0;
        l1 = l1 * cr1 + rs1;
#pragma unroll
        for (int nt = 0; nt < 8; nt++) {
            oacc[nt][0] *= cr0; oacc[nt][1] *= cr0;
            oacc[nt][2] *= cr1; oacc[nt][3] *= cr1;
        }

        // O += P V  (P from S frags, split hi/lo; V frags via ldmatrix.trans)
#pragma unroll
        for (int j = 0; j < 4; j++) {
            uint32_t ph[4], pl[4];
            split_pack(s[2 * j][0], s[2 * j][1], ph[0], pl[0]);
            split_pack(s[2 * j][2], s[2 * j][3], ph[1], pl[1]);
            split_pack(s[2 * j + 1][0], s[2 * j + 1][1], ph[2], pl[2]);
            split_pack(s[2 * j + 1][2], s[2 * j + 1][3], ph[3], pl[3]);
#pragma unroll
            for (int nt = 0; nt < 8; nt++) {
                uint32_t a = stb + 2 * KVBUF + (uint32_t)((j * 16 + (lane & 15)) * FROWB + nt * 16);
                uint32_t vh2[2], vl2[2];
                ldsm2t(vh2, a);
                ldsm2t(vl2, a + KVBUF);
                mma16816(oacc[nt], ph, vh2);
                mma16816(oacc[nt], ph, vl2);
                mma16816(oacc[nt], pl, vh2);
            }
        }
        __syncthreads();   // compute done before the other stage is overwritten
    }

    // epilogue: normalize, split to bf16 hi/lo, store
    const float inv0 = 1.0f / l0, inv1 = 1.0f / l1;
    const int row0 = q0 + wid * 16 + (lane >> 2);
    const int colb = (lane & 3) * 2;
#pragma unroll
    for (int nt = 0; nt < 8; nt++) {
        size_t p0 = base + (size_t)row0 * DM + nt * 8 + colb;
        size_t p1 = p0 + 8 * (size_t)DM;
        uint32_t hp, lp;
        split_pack(oacc[nt][0] * inv0, oacc[nt][1] * inv0, hp, lp);
        *reinterpret_cast<uint32_t*>(oh + p0) = hp;
        *reinterpret_cast<uint32_t*>(ol + p0) = lp;
        split_pack(oacc[nt][2] * inv1, oacc[nt][3] * inv1, hp, lp);
        *reinterpret_cast<uint32_t*>(oh + p1) = hp;
        *reinterpret_cast<uint32_t*>(ol + p1) = lp;
    }
}

// ---------------- launch ----------------
extern "C" void kernel_launch(void* const* d_in, const int* in_sizes, int n_in,
                              void* d_out, int out_size) {
    const float* x  = (const float*)d_in[0];
    const float* W[4] = {(const float*)d_in[1], (const float*)d_in[2],
                         (const float*)d_in[3], (const float*)d_in[4]};
    float* out = (float*)d_out;

    __nv_bfloat16 *qhi, *qlo, *khi, *klo, *vhi, *vlo, *ahi, *alo, *xhi, *xlo, *whi, *wlo;
    cudaGetSymbolAddress((void**)&qhi, g_qhi); cudaGetSymbolAddress((void**)&qlo, g_qlo);
    cudaGetSymbolAddress((void**)&khi, g_khi); cudaGetSymbolAddress((void**)&klo, g_klo);
    cudaGetSymbolAddress((void**)&vhi, g_vhi); cudaGetSymbolAddress((void**)&vlo, g_vlo);
    cudaGetSymbolAddress((void**)&ahi, g_ahi); cudaGetSymbolAddress((void**)&alo, g_alo);
    cudaGetSymbolAddress((void**)&xhi, g_xhi); cudaGetSymbolAddress((void**)&xlo, g_xlo);
    cudaGetSymbolAddress((void**)&whi, g_whi); cudaGetSymbolAddress((void**)&wlo, g_wlo);

    cudaFuncSetAttribute(gemm_mma<true>,  cudaFuncAttributeMaxDynamicSharedMemorySize, GSMEM);
    cudaFuncSetAttribute(gemm_mma<false>, cudaFuncAttributeMaxDynamicSharedMemorySize, GSMEM);
    cudaFuncSetAttribute(flash_mma, cudaFuncAttributeMaxDynamicSharedMemorySize, FSMEM2);

    // splits of inputs
    split_kernel<<<NELEM_X / 4 / 256, 256>>>(x, xhi, xlo, NELEM_X / 4);
    for (int i = 0; i < 4; i++)
        split_kernel<<<NELEM_W / 4 / 256, 256>>>(W[i], whi + (size_t)i * NELEM_W,
                                                 wlo + (size_t)i * NELEM_W, NELEM_W / 4);

    dim3 gGrid(DM / 128, MROWS / 128);   // (8, 32)
    // QKV projections -> bf16 hi/lo directly
    gemm_mma<true><<<gGrid, 256, GSMEM>>>(xhi, xlo, whi + 0 * (size_t)NELEM_W, wlo + 0 * (size_t)NELEM_W,
                                          nullptr, qhi, qlo, MROWS, DM, DM);
    gemm_mma<true><<<gGrid, 256, GSMEM>>>(xhi, xlo, whi + 1 * (size_t)NELEM_W, wlo + 1 * (size_t)NELEM_W,
                                          nullptr, khi, klo, MROWS, DM, DM);
    gemm_mma<true><<<gGrid, 256, GSMEM>>>(xhi, xlo, whi + 2 * (size_t)NELEM_W, wlo + 2 * (size_t)NELEM_W,
                                          nullptr, vhi, vlo, MROWS, DM, DM);

    dim3 fGrid(TT / FBR, BB * NH);       // (16, 32)
    flash_mma<<<fGrid, 256, FSMEM2>>>(qhi, qlo, khi, klo, vhi, vlo, ahi, alo);

    // output projection -> fp32
    gemm_mma<false><<<gGrid, 256, GSMEM>>>(ahi, alo, whi + 3 * (size_t)NELEM_W, wlo + 3 * (size_t)NELEM_W,
                                           out, nullptr, nullptr, MROWS, DM, DM);
}

// round 8
// speedup vs baseline: 2.9324x; 1.0223x over previous
#include <cuda_runtime.h>
#include <cuda_bf16.h>
#include <cstdint>

// Problem constants
#define BB 2
#define TT 2048
#define DM 1024
#define NH 16
#define HD 64
#define MROWS (BB * TT)          // 4096
#define NELEM_X (MROWS * DM)     // 4194304
#define NELEM_W (DM * DM)        // 1048576

// ---------------- scratch (no allocation allowed) ----------------
__device__ __nv_bfloat16 g_qhi[NELEM_X], g_qlo[NELEM_X];
__device__ __nv_bfloat16 g_khi[NELEM_X], g_klo[NELEM_X];
__device__ __nv_bfloat16 g_vhi[NELEM_X], g_vlo[NELEM_X];
__device__ __nv_bfloat16 g_ahi[NELEM_X], g_alo[NELEM_X];
__device__ __nv_bfloat16 g_xhi[NELEM_X], g_xlo[NELEM_X];
__device__ __nv_bfloat16 g_whi[4][NELEM_W], g_wlo[4][NELEM_W];

// ---------------- helpers ----------------
__device__ __forceinline__ uint32_t smem_u32(const void* p) {
    uint32_t a;
    asm("{ .reg .u64 t; cvta.to.shared.u64 t, %1; cvt.u32.u64 %0, t; }" : "=r"(a) : "l"(p));
    return a;
}
__device__ __forceinline__ void cp_async16(uint32_t saddr, const void* gptr) {
    asm volatile("cp.async.cg.shared.global [%0], [%1], 16;" :: "r"(saddr), "l"(gptr));
}
__device__ __forceinline__ void ldsm4(uint32_t* r, uint32_t addr) {
    asm volatile("ldmatrix.sync.aligned.m8n8.x4.shared.b16 {%0,%1,%2,%3}, [%4];"
                 : "=r"(r[0]), "=r"(r[1]), "=r"(r[2]), "=r"(r[3]) : "r"(addr));
}
__device__ __forceinline__ void ldsm2(uint32_t* r, uint32_t addr) {
    asm volatile("ldmatrix.sync.aligned.m8n8.x2.shared.b16 {%0,%1}, [%2];"
                 : "=r"(r[0]), "=r"(r[1]) : "r"(addr));
}
__device__ __forceinline__ void ldsm2t(uint32_t* r, uint32_t addr) {
    asm volatile("ldmatrix.sync.aligned.m8n8.x2.trans.shared.b16 {%0,%1}, [%2];"
                 : "=r"(r[0]), "=r"(r[1]) : "r"(addr));
}
__device__ __forceinline__ void mma16816(float* d, const uint32_t* a, const uint32_t* b) {
    asm volatile("mma.sync.aligned.m16n8k16.row.col.f32.bf16.bf16.f32 "
                 "{%0,%1,%2,%3},{%4,%5,%6,%7},{%8,%9},{%0,%1,%2,%3};"
                 : "+f"(d[0]), "+f"(d[1]), "+f"(d[2]), "+f"(d[3])
                 : "r"(a[0]), "r"(a[1]), "r"(a[2]), "r"(a[3]), "r"(b[0]), "r"(b[1]));
}
__device__ __forceinline__ void split_pack(float a, float b, uint32_t& hp, uint32_t& lp) {
    __nv_bfloat16 ha = __float2bfloat16(a), hb = __float2bfloat16(b);
    __nv_bfloat16 la = __float2bfloat16(a - __bfloat162float(ha));
    __nv_bfloat16 lb = __float2bfloat16(b - __bfloat162float(hb));
    hp = ((uint32_t)__bfloat16_as_ushort(hb) << 16) | __bfloat16_as_ushort(ha);
    lp = ((uint32_t)__bfloat16_as_ushort(lb) << 16) | __bfloat16_as_ushort(la);
}

// ---------------- split fp32 -> bf16 hi/lo ----------------
__global__ __launch_bounds__(256) void split_kernel(const float* __restrict__ in,
                                                    __nv_bfloat16* __restrict__ hi,
                                                    __nv_bfloat16* __restrict__ lo,
                                                    int n4) {
    int i = blockIdx.x * 256 + threadIdx.x;
    if (i >= n4) return;
    float4 v = reinterpret_cast<const float4*>(in)[i];
    uint32_t h0, l0, h1, l1;
    split_pack(v.x, v.y, h0, l0);
    split_pack(v.z, v.w, h1, l1);
    uint32_t* hp = reinterpret_cast<uint32_t*>(hi);
    uint32_t* lp = reinterpret_cast<uint32_t*>(lo);
    hp[2 * i + 0] = h0; hp[2 * i + 1] = h1;
    lp[2 * i + 0] = l0; lp[2 * i + 1] = l1;
}

// ---------------- mma.sync bf16x3 GEMM: C = (Ahi+Alo)(Bhi+Blo)^T --------------
// 128x128 CTA tile, 8 warps (64x32 each), K-chunk 64, 3-stage cp.async pipeline,
// one __syncthreads per chunk. Rows padded to 144 B (conflict-free ldmatrix).
#define GKC 64
#define ROWB 144
#define BUFB (128 * ROWB)            // 18432
#define STGB (4 * BUFB)              // 73728
#define GSMEM (3 * STGB)             // 221184

template<bool SPLITOUT>
__global__ __launch_bounds__(256) void gemm_mma(const __nv_bfloat16* __restrict__ Ahi,
                                                const __nv_bfloat16* __restrict__ Alo,
                                                const __nv_bfloat16* __restrict__ Bhi,
                                                const __nv_bfloat16* __restrict__ Blo,
                                                float* __restrict__ C,
                                                __nv_bfloat16* __restrict__ Chi,
                                                __nv_bfloat16* __restrict__ Clo,
                                                int M, int N, int K) {
    extern __shared__ char smem[];
    const uint32_t sbase = smem_u32(smem);
    const int tid = threadIdx.x;
    const int wid = tid >> 5;
    const int lane = tid & 31;
    const int warp_m = (wid & 1) * 64;
    const int warp_n = (wid >> 1) * 32;
    const int rowBase = blockIdx.y * 128;
    const int colBase = blockIdx.x * 128;

    const __nv_bfloat16* srcs[4];
    srcs[0] = Ahi + (size_t)rowBase * K;
    srcs[1] = Alo + (size_t)rowBase * K;
    srcs[2] = Bhi + (size_t)colBase * K;
    srcs[3] = Blo + (size_t)colBase * K;

    float acc[16][4];
#pragma unroll
    for (int i = 0; i < 16; i++)
#pragma unroll
        for (int j = 0; j < 4; j++) acc[i][j] = 0.0f;

    const int NCH = K / GKC;   // 16

    auto issue = [&](int chunk) {
        const uint32_t stb = sbase + (uint32_t)(chunk % 3) * STGB;
        const int k0 = chunk * GKC;
#pragma unroll
        for (int t = 0; t < 16; t++) {
            int idx = tid + t * 256;        // 4 bufs x 128 rows x 8 c16
            int b = idx >> 10;
            int pos = idx & 1023;
            int r = pos >> 3;
            int c8 = pos & 7;
            cp_async16(stb + (uint32_t)b * BUFB + (uint32_t)(r * ROWB + c8 * 16),
                       srcs[b] + (size_t)r * K + k0 + c8 * 8);
        }
        asm volatile("cp.async.commit_group;" ::: "memory");
    };

    issue(0);
    issue(1);
    for (int i = 0; i < NCH; i++) {
        if (i + 1 < NCH) {
            asm volatile("cp.async.wait_group 1;" ::: "memory");
        } else {
            asm volatile("cp.async.wait_group 0;" ::: "memory");
        }
        __syncthreads();   // stage i readable by all; all threads past compute i-1
        if (i + 2 < NCH) issue(i + 2);   // overwrites stage last read in compute i-1

        const uint32_t stb = sbase + (uint32_t)(i % 3) * STGB;
        const int lm = lane & 15, lk = lane >> 4;
        const int ln = lane & 7, lkb = (lane >> 3) & 1;
#pragma unroll
        for (int ks = 0; ks < 4; ks++) {
            uint32_t ah[4][4], al[4][4], bh[4][2], bl[4][2];
#pragma unroll
            for (int mt = 0; mt < 4; mt++) {
                uint32_t ra = stb + (uint32_t)((warp_m + mt * 16 + lm) * ROWB + ks * 32 + lk * 16);
                ldsm4(ah[mt], ra);
                ldsm4(al[mt], ra + BUFB);
            }
#pragma unroll
            for (int nt = 0; nt < 4; nt++) {
                uint32_t rb = stb + 2 * BUFB + (uint32_t)((warp_n + nt * 8 + ln) * ROWB + ks * 32 + lkb * 16);
                ldsm2(bh[nt], rb);
                ldsm2(bl[nt], rb + BUFB);
            }
#pragma unroll
            for (int mt = 0; mt < 4; mt++)
#pragma unroll
                for (int nt = 0; nt < 4; nt++) {
                    mma16816(acc[mt * 4 + nt], ah[mt], bh[nt]);
                    mma16816(acc[mt * 4 + nt], ah[mt], bl[nt]);
                    mma16816(acc[mt * 4 + nt], al[mt], bh[nt]);
                }
        }
    }

    const int mrow = rowBase + warp_m + (lane >> 2);
    const int ncol = colBase + warp_n + (lane & 3) * 2;
#pragma unroll
    for (int mt = 0; mt < 4; mt++)
#pragma unroll
        for (int nt = 0; nt < 4; nt++) {
            const float* a = acc[mt * 4 + nt];
            size_t p0 = (size_t)(mrow + mt * 16) * N + ncol + nt * 8;
            size_t p1 = p0 + 8 * (size_t)N;
            if (!SPLITOUT) {
                *reinterpret_cast<float2*>(C + p0) = make_float2(a[0], a[1]);
                *reinterpret_cast<float2*>(C + p1) = make_float2(a[2], a[3]);
            } else {
                uint32_t hp, lp;
                split_pack(a[0], a[1], hp, lp);
                *reinterpret_cast<uint32_t*>(Chi + p0) = hp;
                *reinterpret_cast<uint32_t*>(Clo + p0) = lp;
                split_pack(a[2], a[3], hp, lp);
                *reinterpret_cast<uint32_t*>(Chi + p1) = hp;
                *reinterpret_cast<uint32_t*>(Clo + p1) = lp;
            }
        }
}

// ---------------- Flash attention via mma.sync (causal) ----------------
// Br=128, Bc=64, D=64. 8 warps, warp-local softmax. bf16x3 QK^T and PV.
// 3 KV stages, one __syncthreads per key tile.
#define FBR 128
#define FBC 64
#define FROWB 144
#define QBUF (FBR * FROWB)           // 18432
#define KVBUF (FBC * FROWB)          // 9216
#define FKV0 (2 * QBUF)              // 36864
#define FSTG (4 * KVBUF)             // 36864
#define FSMEM2 (FKV0 + 3 * FSTG)     // 147456

__global__ __launch_bounds__(256, 1) void flash_mma(
    const __nv_bfloat16* __restrict__ qh, const __nv_bfloat16* __restrict__ ql,
    const __nv_bfloat16* __restrict__ kh, const __nv_bfloat16* __restrict__ kl,
    const __nv_bfloat16* __restrict__ vh, const __nv_bfloat16* __restrict__ vl,
    __nv_bfloat16* __restrict__ oh, __nv_bfloat16* __restrict__ ol) {
    extern __shared__ char smem[];
    const uint32_t sbase = smem_u32(smem);
    const int tid = threadIdx.x;
    const int wid = tid >> 5;
    const int lane = tid & 31;
    const int qt = blockIdx.x;
    const int bh = blockIdx.y;
    const int b = bh >> 4, h = bh & 15;
    const size_t base = (size_t)b * TT * DM + h * HD;
    const int q0 = qt * FBR;

    const __nv_bfloat16* mats[4] = {kh, kl, vh, vl};
    auto issue_kv_nocommit = [&](int kt) {
        const uint32_t stb = sbase + FKV0 + (uint32_t)(kt % 3) * FSTG;
        const int t0 = kt * FBC;
#pragma unroll
        for (int t = 0; t < 8; t++) {
            int idx = tid + t * 256;               // 4 mats x 64 rows x 8 c16
            int mat = idx >> 9;
            int pos = idx & 511;
            int r = pos >> 3, c8 = pos & 7;
            cp_async16(stb + (uint32_t)(mat * KVBUF + r * FROWB + c8 * 16),
                       mats[mat] + base + (size_t)(t0 + r) * DM + c8 * 8);
        }
    };

    // group 0: Q (hi/lo) + KV tile 0
#pragma unroll
    for (int t = 0; t < 8; t++) {
        int idx = tid + t * 256;
        int mat = idx >> 10;
        int pos = idx & 1023;
        int r = pos >> 3, c8 = pos & 7;
        const __nv_bfloat16* src = (mat ? ql : qh) + base + (size_t)(q0 + r) * DM + c8 * 8;
        cp_async16(sbase + (uint32_t)(mat * QBUF + r * FROWB + c8 * 16), src);
    }
    issue_kv_nocommit(0);
    asm volatile("cp.async.commit_group;" ::: "memory");

    const int NKT = 2 * (qt + 1);
    if (NKT > 1) {
        issue_kv_nocommit(1);
        asm volatile("cp.async.commit_group;" ::: "memory");
    }

    uint32_t qfh[4][4], qfl[4][4];
    float m0 = -1e30f, m1 = -1e30f, l0 = 0.0f, l1 = 0.0f;
    float oacc[8][4];
#pragma unroll
    for (int i = 0; i < 8; i++)
#pragma unroll
        for (int j = 0; j < 4; j++) oacc[i][j] = 0.0f;

    for (int kt = 0; kt < NKT; kt++) {
        if (kt + 1 < NKT) {
            asm volatile("cp.async.wait_group 1;" ::: "memory");
        } else {
            asm volatile("cp.async.wait_group 0;" ::: "memory");
        }
        __syncthreads();
        if (kt == 0) {
            // Q fragments (persistent)
#pragma unroll
            for (int ks = 0; ks < 4; ks++) {
                uint32_t a = sbase + (uint32_t)((wid * 16 + (lane & 15)) * FROWB + ks * 32 + (lane >> 4) * 16);
                ldsm4(qfh[ks], a);
                ldsm4(qfl[ks], a + QBUF);
            }
        }
        if (kt + 2 < NKT) {
            issue_kv_nocommit(kt + 2);
            asm volatile("cp.async.commit_group;" ::: "memory");
        }
        const uint32_t stb = sbase + FKV0 + (uint32_t)(kt % 3) * FSTG;

        // S = Q K^T (bf16x3)
        float s[8][4];
#pragma unroll
        for (int i = 0; i < 8; i++)
#pragma unroll
            for (int j = 0; j < 4; j++) s[i][j] = 0.0f;
#pragma unroll
        for (int ks = 0; ks < 4; ks++) {
#pragma unroll
            for (int nt = 0; nt < 8; nt++) {
                uint32_t a = stb + (uint32_t)((nt * 8 + (lane & 7)) * FROWB + ks * 32 + ((lane >> 3) & 1) * 16);
                uint32_t kh2[2], kl2[2];
                ldsm2(kh2, a);
                ldsm2(kl2, a + KVBUF);
                mma16816(s[nt], qfh[ks], kh2);
                mma16816(s[nt], qfh[ks], kl2);
                mma16816(s[nt], qfl[ks], kh2);
            }
        }

        // scale + causal mask
        const int r0g = q0 + wid * 16 + (lane >> 2);
        const bool need_mask = (kt >= 2 * qt);
#pragma unroll
        for (int nt = 0; nt < 8; nt++)
#pragma unroll
            for (int c = 0; c < 4; c++) {
                float val = s[nt][c] * 0.125f;
                if (need_mask) {
                    int col = kt * 64 + nt * 8 + (lane & 3) * 2 + (c & 1);
                    int row = r0g + (c >> 1) * 8;
                    if (col > row) val = -1e30f;
                }
                s[nt][c] = val;
            }

        // online softmax (rows r0 -> c0,c1; r0+8 -> c2,c3)
        float mx0 = -1e30f, mx1 = -1e30f;
#pragma unroll
        for (int nt = 0; nt < 8; nt++) {
            mx0 = fmaxf(mx0, fmaxf(s[nt][0], s[nt][1]));
            mx1 = fmaxf(mx1, fmaxf(s[nt][2], s[nt][3]));
        }
        mx0 = fmaxf(mx0, __shfl_xor_sync(0xffffffffu, mx0, 1));
        mx0 = fmaxf(mx0, __shfl_xor_sync(0xffffffffu, mx0, 2));
        mx1 = fmaxf(mx1, __shfl_xor_sync(0xffffffffu, mx1, 1));
        mx1 = fmaxf(mx1, __shfl_xor_sync(0xffffffffu, mx1, 2));
        float nm0 = fmaxf(m0, mx0), nm1 = fmaxf(m1, mx1);
        float cr0 = __expf(m0 - nm0), cr1 = __expf(m1 - nm1);
        m0 = nm0; m1 = nm1;
        float rs0 = 0.0f, rs1 = 0.0f;
#pragma unroll
        for (int nt = 0; nt < 8; nt++) {
            s[nt][0] = __expf(s[nt][0] - nm0);
            s[nt][1] = __expf(s[nt][1] - nm0);
            s[nt][2] = __expf(s[nt][2] - nm1);
            s[nt][3] = __expf(s[nt][3] - nm1);
            rs0 += s[nt][0] + s[nt][1];
            rs1 += s[nt][2] + s[nt][3];
        }
        rs0 += __shfl_xor_sync(0xffffffffu, rs0, 1);
        rs0 += __shfl_xor_sync(0xffffffffu, rs0, 2);
        rs1 += __shfl_xor_sync(0xffffffffu, rs1, 1);
        rs1 += __shfl_xor_sync(0xffffffffu, rs1, 2);
        l0 = l0 * cr0 + rs0;
        l1 = l1 * cr1 + rs1;
#pragma unroll
        for (int nt = 0; nt < 8; nt++) {
            oacc[nt][0] *= cr0; oacc[nt][1] *= cr0;
            oacc[nt][2] *= cr1; oacc[nt][3] *= cr1;
        }

        // O += P V
#pragma unroll
        for (int j = 0; j < 4; j++) {
            uint32_t ph[4], pl[4];
            split_pack(s[2 * j][0], s[2 * j][1], ph[0], pl[0]);
            split_pack(s[2 * j][2], s[2 * j][3], ph[1], pl[1]);
            split_pack(s[2 * j + 1][0], s[2 * j + 1][1], ph[2], pl[2]);
            split_pack(s[2 * j + 1][2], s[2 * j + 1][3], ph[3], pl[3]);
#pragma unroll
            for (int nt = 0; nt < 8; nt++) {
                uint32_t a = stb + 2 * KVBUF + (uint32_t)((j * 16 + (lane & 15)) * FROWB + nt * 16);
                uint32_t vh2[2], vl2[2];
                ldsm2t(vh2, a);
                ldsm2t(vl2, a + KVBUF);
                mma16816(oacc[nt], ph, vh2);
                mma16816(oacc[nt], ph, vl2);
                mma16816(oacc[nt], pl, vh2);
            }
        }
    }

    // epilogue: normalize, split to bf16 hi/lo, store
    const float inv0 = 1.0f / l0, inv1 = 1.0f / l1;
    const int row0 = q0 + wid * 16 + (lane >> 2);
    const int colb = (lane & 3) * 2;
#pragma unroll
    for (int nt = 0; nt < 8; nt++) {
        size_t p0 = base + (size_t)row0 * DM + nt * 8 + colb;
        size_t p1 = p0 + 8 * (size_t)DM;
        uint32_t hp, lp;
        split_pack(oacc[nt][0] * inv0, oacc[nt][1] * inv0, hp, lp);
        *reinterpret_cast<uint32_t*>(oh + p0) = hp;
        *reinterpret_cast<uint32_t*>(ol + p0) = lp;
        split_pack(oacc[nt][2] * inv1, oacc[nt][3] * inv1, hp, lp);
        *reinterpret_cast<uint32_t*>(oh + p1) = hp;
        *reinterpret_cast<uint32_t*>(ol + p1) = lp;
    }
}

// ---------------- launch ----------------
extern "C" void kernel_launch(void* const* d_in, const int* in_sizes, int n_in,
                              void* d_out, int out_size) {
    const float* x  = (const float*)d_in[0];
    const float* W[4] = {(const float*)d_in[1], (const float*)d_in[2],
                         (const float*)d_in[3], (const float*)d_in[4]};
    float* out = (float*)d_out;

    __nv_bfloat16 *qhi, *qlo, *khi, *klo, *vhi, *vlo, *ahi, *alo, *xhi, *xlo, *whi, *wlo;
    cudaGetSymbolAddress((void**)&qhi, g_qhi); cudaGetSymbolAddress((void**)&qlo, g_qlo);
    cudaGetSymbolAddress((void**)&khi, g_khi); cudaGetSymbolAddress((void**)&klo, g_klo);
    cudaGetSymbolAddress((void**)&vhi, g_vhi); cudaGetSymbolAddress((void**)&vlo, g_vlo);
    cudaGetSymbolAddress((void**)&ahi, g_ahi); cudaGetSymbolAddress((void**)&alo, g_alo);
    cudaGetSymbolAddress((void**)&xhi, g_xhi); cudaGetSymbolAddress((void**)&xlo, g_xlo);
    cudaGetSymbolAddress((void**)&whi, g_whi); cudaGetSymbolAddress((void**)&wlo, g_wlo);

    cudaFuncSetAttribute(gemm_mma<true>,  cudaFuncAttributeMaxDynamicSharedMemorySize, GSMEM);
    cudaFuncSetAttribute(gemm_mma<false>, cudaFuncAttributeMaxDynamicSharedMemorySize, GSMEM);
    cudaFuncSetAttribute(flash_mma, cudaFuncAttributeMaxDynamicSharedMemorySize, FSMEM2);

    // splits of inputs
    split_kernel<<<NELEM_X / 4 / 256, 256>>>(x, xhi, xlo, NELEM_X / 4);
    for (int i = 0; i < 4; i++)
        split_kernel<<<NELEM_W / 4 / 256, 256>>>(W[i], whi + (size_t)i * NELEM_W,
                                                 wlo + (size_t)i * NELEM_W, NELEM_W / 4);

    dim3 gGrid(DM / 128, MROWS / 128);   // (8, 32)
    gemm_mma<true><<<gGrid, 256, GSMEM>>>(xhi, xlo, whi + 0 * (size_t)NELEM_W, wlo + 0 * (size_t)NELEM_W,
                                          nullptr, qhi, qlo, MROWS, DM, DM);
    gemm_mma<true><<<gGrid, 256, GSMEM>>>(xhi, xlo, whi + 1 * (size_t)NELEM_W, wlo + 1 * (size_t)NELEM_W,
                                          nullptr, khi, klo, MROWS, DM, DM);
    gemm_mma<true><<<gGrid, 256, GSMEM>>>(xhi, xlo, whi + 2 * (size_t)NELEM_W, wlo + 2 * (size_t)NELEM_W,
                                          nullptr, vhi, vlo, MROWS, DM, DM);

    dim3 fGrid(TT / FBR, BB * NH);       // (16, 32)
    flash_mma<<<fGrid, 256, FSMEM2>>>(qhi, qlo, khi, klo, vhi, vlo, ahi, alo);

    gemm_mma<false><<<gGrid, 256, GSMEM>>>(ahi, alo, whi + 3 * (size_t)NELEM_W, wlo + 3 * (size_t)NELEM_W,
                                           out, nullptr, nullptr, MROWS, DM, DM);
}